// round 2
// baseline (speedup 1.0000x reference)
#include <cuda_runtime.h>

// Problem constants
#define FM_H 38
#define FM_W 50
#define FM_C 512
#define N_ROI 512
#define POOL 7          // 7x7 pooled output
#define CROP 14         // 14x14 crop grid (2x2 pooled)
#define IMW 800.0f
#define IMH 600.0f

// Each block computes one (roi, pooled_y, pooled_x) cell for all 512 channels.
// 128 threads x float4 = 512 channels. 16 coalesced float4 tap loads per thread.
__global__ __launch_bounds__(128) void roi_pool_kernel(
    const float* __restrict__ fm,     // [38,50,512]
    const float* __restrict__ rois,   // [512,5] (0, x1, y1, x2, y2)
    float* __restrict__ out)          // [512,7,7,512]
{
    const int cell = blockIdx.x;          // 0..48
    const int roi  = blockIdx.y;          // 0..511
    const int py   = cell / POOL;
    const int px   = cell - py * POOL;
    const int t    = threadIdx.x;         // channel group: c = 4*t

    // Normalized box, matching reference ordering.
    const float* r = rois + roi * 5;
    const float x1n = r[1] / IMW;
    const float y1n = r[2] / IMH;
    const float x2n = r[3] / IMW;
    const float y2n = r[4] / IMH;
    const float dy = y2n - y1n;
    const float dx = x2n - x1n;

    // Precompute the 2 crop rows and 2 crop cols for this pooled cell.
    int   yi0[2], yi1[2], xi0[2], xi1[2];
    float wy[2], wx[2];
#pragma unroll
    for (int d = 0; d < 2; ++d) {
        // row
        {
            const int iy = 2 * py + d;
            const float ty = (float)iy / (float)(CROP - 1);
            const float ys = (y1n + ty * dy) * (float)(FM_H - 1);
            const float yf = floorf(ys);
            int y0 = (int)yf;
            y0 = min(max(y0, 0), FM_H - 1);
            yi0[d] = y0;
            yi1[d] = min(y0 + 1, FM_H - 1);
            wy[d]  = ys - yf;
        }
        // col
        {
            const int ix = 2 * px + d;
            const float tx = (float)ix / (float)(CROP - 1);
            const float xs = (x1n + tx * dx) * (float)(FM_W - 1);
            const float xf = floorf(xs);
            int x0 = (int)xf;
            x0 = min(max(x0, 0), FM_W - 1);
            xi0[d] = x0;
            xi1[d] = min(x0 + 1, FM_W - 1);
            wx[d]  = xs - xf;
        }
    }

    float4 acc = make_float4(-3.402823466e+38f, -3.402823466e+38f,
                             -3.402823466e+38f, -3.402823466e+38f);

    const float4* fm4 = (const float4*)fm;  // [38*50, 128] float4 rows of 128

#pragma unroll
    for (int dyi = 0; dyi < 2; ++dyi) {
#pragma unroll
        for (int dxi = 0; dxi < 2; ++dxi) {
            const float wyv = wy[dyi];
            const float wxv = wx[dxi];
            const int r0 = yi0[dyi] * FM_W;
            const int r1 = yi1[dyi] * FM_W;
            const float4 v00 = fm4[(size_t)(r0 + xi0[dxi]) * 128 + t];
            const float4 v01 = fm4[(size_t)(r0 + xi1[dxi]) * 128 + t];
            const float4 v10 = fm4[(size_t)(r1 + xi0[dxi]) * 128 + t];
            const float4 v11 = fm4[(size_t)(r1 + xi1[dxi]) * 128 + t];

            // top = v00*(1-wx) + v01*wx ; bot = v10*(1-wx) + v11*wx
            // val = top*(1-wy) + bot*wy
            float4 val;
            {
                float top = v00.x * (1.0f - wxv) + v01.x * wxv;
                float bot = v10.x * (1.0f - wxv) + v11.x * wxv;
                val.x = top * (1.0f - wyv) + bot * wyv;
            }
            {
                float top = v00.y * (1.0f - wxv) + v01.y * wxv;
                float bot = v10.y * (1.0f - wxv) + v11.y * wxv;
                val.y = top * (1.0f - wyv) + bot * wyv;
            }
            {
                float top = v00.z * (1.0f - wxv) + v01.z * wxv;
                float bot = v10.z * (1.0f - wxv) + v11.z * wxv;
                val.z = top * (1.0f - wyv) + bot * wyv;
            }
            {
                float top = v00.w * (1.0f - wxv) + v01.w * wxv;
                float bot = v10.w * (1.0f - wxv) + v11.w * wxv;
                val.w = top * (1.0f - wyv) + bot * wyv;
            }
            acc.x = fmaxf(acc.x, val.x);
            acc.y = fmaxf(acc.y, val.y);
            acc.z = fmaxf(acc.z, val.z);
            acc.w = fmaxf(acc.w, val.w);
        }
    }

    float4* out4 = (float4*)out;
    out4[((size_t)(roi * POOL + py) * POOL + px) * 128 + t] = acc;
}

extern "C" void kernel_launch(void* const* d_in, const int* in_sizes, int n_in,
                              void* d_out, int out_size)
{
    const float* fm   = (const float*)d_in[0];   // feature_maps [1,38,50,512]
    const float* rois = (const float*)d_in[1];   // [512,5]
    float* out = (float*)d_out;                  // [1,512,7,7,512]

    dim3 grid(POOL * POOL, N_ROI);
    roi_pool_kernel<<<grid, 128>>>(fm, rois, out);
}